// round 13
// baseline (speedup 1.0000x reference)
#include <cuda_runtime.h>
#include <cuda_bf16.h>
#include <cuda_fp16.h>
#include <math.h>
#include <stdint.h>

// Problem constants (fixed by the dataset)
#define NMAX 100000
#define EMAX 1600000
#define F    128
#define G    64
#define OUTD 10

// ---------------- device scratch (static, no allocation) ----------------
__device__ float   g_bufA[(size_t)NMAX * F];    // GEMM output h (fp32, self term)
__device__ __half2 g_bufA16[(size_t)NMAX * 64]; // GEMM output h (fp16, gathers)
__device__ float   g_bufB[(size_t)NMAX * F];    // layer output (fp32, pool/self)
__device__ __half2 g_bufB16[(size_t)NMAX * 64]; // layer output (fp16, next GEMM A)
__device__ __half2 g_x16[(size_t)NMAX * 64];    // x converted to fp16 (layer-1 A)
__device__ uint2   g_Ws[3][128 * 64];           // pre-split W: [nn][kc] {hi2,lo2}
__device__ float   g_dinv[NMAX];
__device__ int     g_deg[NMAX];                 // degree incl. self loop
__device__ int     g_scan[NMAX];
__device__ int     g_bsum[128];
__device__ int     g_rowstart[NMAX];
__device__ int     g_pos[NMAX];
__device__ float2  g_edge[EMAX];                // packed (src as int bits, norm)
__device__ float   g_gsum[G * F];
__device__ int     g_gcnt[G];

__device__ __forceinline__ int clampi(int v, int lo, int hi) {
    return v < lo ? lo : (v > hi ? hi : v);
}

__device__ __forceinline__ void mma_f16(float* c, const uint32_t* a,
                                        uint32_t b0, uint32_t b1) {
    asm volatile(
        "mma.sync.aligned.m16n8k16.row.col.f32.f16.f16.f32 "
        "{%0,%1,%2,%3},{%4,%5,%6,%7},{%8,%9},{%0,%1,%2,%3};"
        : "+f"(c[0]), "+f"(c[1]), "+f"(c[2]), "+f"(c[3])
        : "r"(a[0]), "r"(a[1]), "r"(a[2]), "r"(a[3]), "r"(b0), "r"(b1));
}

// ---------------- degree ----------------
__global__ void k_deg_init(int n) {
    int i = blockIdx.x * blockDim.x + threadIdx.x;
    if (i < n) g_deg[i] = 1;            // self loop contributes 1
}

__global__ void k_deg_count(const int* __restrict__ dst, int e, int n) {
    int i = blockIdx.x * blockDim.x + threadIdx.x;
    if (i < e) atomicAdd(&g_deg[clampi(dst[i], 0, n - 1)], 1);
}

// ---------------- W pre-split: {hi,lo} fp16 pairs, [nn][kc] layout ----------------
__global__ void k_wsplit(const float* __restrict__ W0, const float* __restrict__ W1,
                         const float* __restrict__ W2) {
    int i = blockIdx.x * blockDim.x + threadIdx.x;    // 0..49151
    if (i >= 3 * 128 * 64) return;
    int which = i >> 13;                              // 8192 uint2... no: 128*64=8192
    int j     = i & 8191;
    int kc    = j & 63;
    int nn    = j >> 6;
    const float* W = (which == 0) ? W0 : (which == 1) ? W1 : W2;
    float w0 = W[(2 * kc) * 128 + nn];
    float w1 = W[(2 * kc + 1) * 128 + nn];
    __half h0 = __float2half_rn(w0);
    __half h1 = __float2half_rn(w1);
    __half l0 = __float2half_rn(w0 - __half2float(h0));
    __half l1 = __float2half_rn(w1 - __half2float(h1));
    __half2 hp = __halves2half2(h0, h1);
    __half2 lp = __halves2half2(l0, l1);
    uint2 q;
    q.x = *(uint32_t*)&hp;
    q.y = *(uint32_t*)&lp;
    g_Ws[which][nn * 64 + kc] = q;
}

// ---------------- x -> fp16 ----------------
__global__ void k_x16(const float* __restrict__ x, int n) {
    int i = blockIdx.x * blockDim.x + threadIdx.x;   // half2 units: n*64
    if (i < n * 64) {
        float2 v = ((const float2*)x)[i];
        g_x16[i] = __float22half2_rn(v);
    }
}

// ---------------- scan1 (+dinv fused) ----------------
__global__ void k_scan1(int n) {                 // 1024 threads/block
    __shared__ int sh[1024];
    int gid = blockIdx.x * 1024 + threadIdx.x;
    int deg = (gid < n) ? g_deg[gid] : 1;
    if (gid < n) g_dinv[gid] = rsqrtf((float)deg);
    int v = (gid < n) ? (deg - 1) : 0;
    sh[threadIdx.x] = v;
    __syncthreads();
    for (int off = 1; off < 1024; off <<= 1) {   // Hillis-Steele inclusive
        int t = (threadIdx.x >= off) ? sh[threadIdx.x - off] : 0;
        __syncthreads();
        sh[threadIdx.x] += t;
        __syncthreads();
    }
    if (gid < n) g_scan[gid] = sh[threadIdx.x];
    if (threadIdx.x == 1023) g_bsum[blockIdx.x] = sh[1023];
}

// ---------------- scan2 (+pool_init fused) ----------------
__global__ void k_scan2(int nb, const int* __restrict__ batch, int n) {  // 1 block, 128 thr
    __shared__ int sh[128];
    int t = threadIdx.x;
    sh[t] = (t < nb) ? g_bsum[t] : 0;
    __syncthreads();
    if (t == 0) {
        int acc = 0;
        for (int i = 0; i < nb; i++) { int v = sh[i]; sh[i] = acc; acc += v; }
    }
    __syncthreads();
    if (t < nb) g_bsum[t] = sh[t];

    // pool init
    for (int i = t; i < G * F; i += blockDim.x) g_gsum[i] = 0.f;
    if (t < G) {
        int lo, hi;
        {
            int a = 0, b = n;
            while (a < b) { int m = (a + b) >> 1; if (batch[m] < t) a = m + 1; else b = m; }
            lo = a;
        }
        {
            int a = 0, b = n;
            while (a < b) { int m = (a + b) >> 1; if (batch[m] < t + 1) a = m + 1; else b = m; }
            hi = a;
        }
        g_gcnt[t] = hi - lo;
    }
}

__global__ void k_scan3(int n) {
    int gid = blockIdx.x * blockDim.x + threadIdx.x;
    if (gid >= n) return;
    int cnt   = g_deg[gid] - 1;
    int start = g_scan[gid] - cnt + g_bsum[gid >> 10];   // exclusive start
    g_rowstart[gid] = start;
    g_pos[gid]      = start;
}

__global__ void k_csr_fill(const int* __restrict__ src, const int* __restrict__ dst,
                           int e, int n) {
    int i = blockIdx.x * blockDim.x + threadIdx.x;
    if (i >= e) return;
    int s = clampi(src[i], 0, n - 1);
    int d = clampi(dst[i], 0, n - 1);
    int slot = atomicAdd(&g_pos[d], 1);
    g_edge[slot] = make_float2(__int_as_float(s), g_dinv[s] * g_dinv[d]);
}

// ---------------- fp16 tensor-core GEMM, W split hi+lo (2 mmas) ----------------
// g_bufA[n x 128] = X[n x 128] @ W[128 x 128]; writes fp32 + fp16 copies.
// Single K pass: full A tile (fp16) + pre-split W (copied from g_Ws) in smem.
#define GAS 68   // half2 per A row (64 + 4 pad)
#define GWS 68   // uint2 per WP row (64 + 4 pad)
#define GEMM_SMEM (128 * GAS * 4 + 128 * GWS * 8)   // 104448 B
__global__ __launch_bounds__(256, 2) void k_gemm_f16(
    int use_ext, int wsel, int nrows)
{
    extern __shared__ char sm_[];
    __half2* A2 = (__half2*)sm_;                      // [128][GAS]  A[m][k-pair]
    uint2*   WP = (uint2*)(sm_ + 128 * GAS * 4);      // [128][GWS]  {hi2,lo2} per n,kc

    const __half2* Xsrc = use_ext ? g_x16 : g_bufB16;
    const uint2*   Ws   = g_Ws[wsel];

    int tid  = threadIdx.x;
    int row0 = blockIdx.x * 128;

    // ---- fill A tile: straight fp16 copy (coalesced 16B chunks) ----
#pragma unroll
    for (int i = 0; i < 8; i++) {
        int c  = tid + i * 256;        // 0..2047 chunks of 4 half2
        int m  = c >> 4;               // 0..127
        int kq = (c & 15) * 4;         // half2 col 0,4,..60
        uint4 v = make_uint4(0u, 0u, 0u, 0u);
        int row = row0 + m;
        if (row < nrows) v = *(const uint4*)(Xsrc + (size_t)row * 64 + kq);
        *(uint4*)(A2 + m * GAS + kq) = v;
    }
    // ---- fill WP: pure uint4 copy of pre-split W ----
#pragma unroll
    for (int i = 0; i < 16; i++) {
        int f  = tid + i * 256;        // 0..4095 uint4 (2 uint2 each)
        int nn = f >> 5;               // 32 uint4 per row
        int kc = (f & 31) * 2;
        uint4 v = *(const uint4*)(Ws + nn * 64 + kc);
        *(uint4*)(WP + nn * GWS + kc) = v;
    }
    __syncthreads();

    int lane = tid & 31;
    int wid  = tid >> 5;
    int g    = lane >> 2;          // 0..7
    int t    = lane & 3;           // 0..3
    int wm   = (wid & 3) * 32;     // warp m offset
    int wn   = (wid >> 2) * 64;    // warp n offset

    float acc[2][8][4];
#pragma unroll
    for (int mi = 0; mi < 2; mi++)
#pragma unroll
        for (int ni = 0; ni < 8; ni++)
#pragma unroll
            for (int q = 0; q < 4; q++) acc[mi][ni][q] = 0.f;

#pragma unroll
    for (int kk = 0; kk < 8; kk++) {           // k16 steps over K=128
        int kb = kk * 8;                       // k-pair base
        uint32_t a[2][4];
#pragma unroll
        for (int mi = 0; mi < 2; mi++) {
            int m = wm + mi * 16;
            a[mi][0] = *(uint32_t*)&A2[(m + g)     * GAS + kb + t];
            a[mi][1] = *(uint32_t*)&A2[(m + g + 8) * GAS + kb + t];
            a[mi][2] = *(uint32_t*)&A2[(m + g)     * GAS + kb + 4 + t];
            a[mi][3] = *(uint32_t*)&A2[(m + g + 8) * GAS + kb + 4 + t];
        }
#pragma unroll
        for (int ni = 0; ni < 8; ni++) {
            int nn = wn + ni * 8 + g;
            uint2 q0 = WP[nn * GWS + kb + t];        // {b0_hi, b0_lo}
            uint2 q1 = WP[nn * GWS + kb + 4 + t];    // {b1_hi, b1_lo}
#pragma unroll
            for (int mi = 0; mi < 2; mi++) {
                mma_f16(acc[mi][ni], a[mi], q0.x, q1.x);   // A * W_hi
                mma_f16(acc[mi][ni], a[mi], q0.y, q1.y);   // A * W_lo
            }
        }
    }

    // ---- write C fragments (fp32 + fp16 copy) ----
#pragma unroll
    for (int mi = 0; mi < 2; mi++) {
#pragma unroll
        for (int ni = 0; ni < 8; ni++) {
            int col = wn + ni * 8 + t * 2;
            int r0  = row0 + wm + mi * 16 + g;
            int r1  = r0 + 8;
            float2 v0 = make_float2(acc[mi][ni][0], acc[mi][ni][1]);
            float2 v1 = make_float2(acc[mi][ni][2], acc[mi][ni][3]);
            if (r0 < nrows) {
                *(float2*)(g_bufA + (size_t)r0 * 128 + col) = v0;
                g_bufA16[(size_t)r0 * 64 + (col >> 1)] = __float22half2_rn(v0);
            }
            if (r1 < nrows) {
                *(float2*)(g_bufA + (size_t)r1 * 128 + col) = v1;
                g_bufA16[(size_t)r1 * 64 + (col >> 1)] = __float22half2_rn(v1);
            }
        }
    }
}

// ---- fused aggregate: bufB[d] = prelu(dinv2*bufA[d] + sum norm*h16[s] + bias) ----
// Warp per dst node; lane owns 4 features. Self term fp32, gathers fp16.
// Two independent edge chains -> MLP=2 gather rows in flight per warp.
__device__ __forceinline__ uint2 row_ld16(float2 ed, int lane) {
    int s = __float_as_int(ed.x);
    return *((const uint2*)(g_bufA16 + (size_t)s * 64) + lane);
}

__device__ __forceinline__ void fma_row16(float4& acc, float nv, uint2 h) {
    float2 p0 = __half22float2(*(const __half2*)&h.x);
    float2 p1 = __half22float2(*(const __half2*)&h.y);
    acc.x = fmaf(nv, p0.x, acc.x);
    acc.y = fmaf(nv, p0.y, acc.y);
    acc.z = fmaf(nv, p1.x, acc.z);
    acc.w = fmaf(nv, p1.y, acc.w);
}

__global__ void k_aggregate(const float* __restrict__ bias,
                            const float* __restrict__ aP, int n, int do_prelu)
{
    int gw   = (blockIdx.x * blockDim.x + threadIdx.x) >> 5;
    int lane = threadIdx.x & 31;
    if (gw >= n) return;

    int   start = g_rowstart[gw];
    int   cnt   = g_deg[gw] - 1;
    float dv    = g_dinv[gw];

    float4 acc = *((const float4*)(g_bufA + (size_t)gw * 128) + lane);
    float  sc  = dv * dv;
    acc.x *= sc; acc.y *= sc; acc.z *= sc; acc.w *= sc;

    if (cnt > 0) {
        int h = cnt >> 1;                       // chain A: [0,h), chain B: [h,cnt)
        float4 acc2 = make_float4(0.f, 0.f, 0.f, 0.f);
        if (h > 0) {
            float2 eA = g_edge[start];
            float2 eB = g_edge[start + h];
            uint2  hA = row_ld16(eA, lane);
            uint2  hB = row_ld16(eB, lane);
            for (int k = 1; k < h; k++) {
                float2 eA1 = g_edge[start + k];
                float2 eB1 = g_edge[start + h + k];
                uint2  hA1 = row_ld16(eA1, lane);
                uint2  hB1 = row_ld16(eB1, lane);
                fma_row16(acc,  eA.y, hA);
                fma_row16(acc2, eB.y, hB);
                eA = eA1; hA = hA1; eB = eB1; hB = hB1;
            }
            fma_row16(acc,  eA.y, hA);
            fma_row16(acc2, eB.y, hB);
            if (cnt & 1) {                      // chain B's extra edge
                float2 eC = g_edge[start + 2 * h];
                fma_row16(acc2, eC.y, row_ld16(eC, lane));
            }
        } else {                                // cnt == 1
            float2 eC = g_edge[start];
            fma_row16(acc, eC.y, row_ld16(eC, lane));
        }
        acc.x += acc2.x; acc.y += acc2.y; acc.z += acc2.z; acc.w += acc2.w;
    }

    float4 b = *((const float4*)bias + lane);
    acc.x += b.x; acc.y += b.y; acc.z += b.z; acc.w += b.w;

    if (do_prelu) {
        float al = aP[0];
        acc.x = acc.x > 0.f ? acc.x : al * acc.x;
        acc.y = acc.y > 0.f ? acc.y : al * acc.y;
        acc.z = acc.z > 0.f ? acc.z : al * acc.z;
        acc.w = acc.w > 0.f ? acc.w : al * acc.w;
    }
    *((float4*)(g_bufB + (size_t)gw * 128) + lane) = acc;

    __half2 o0 = __float22half2_rn(make_float2(acc.x, acc.y));
    __half2 o1 = __float22half2_rn(make_float2(acc.z, acc.w));
    uint2 ov;
    ov.x = *(uint32_t*)&o0;
    ov.y = *(uint32_t*)&o1;
    *((uint2*)(g_bufB16 + (size_t)gw * 64) + lane) = ov;
}

// ---------------- pooling ----------------
// 128 threads per block (one per feature); each block handles 256 nodes.
__global__ void k_pool_sum(const int* __restrict__ batch, int n) {
    int f  = threadIdx.x;                      // 0..127
    int n0 = blockIdx.x * 256;
    int n1 = min(n0 + 256, n);
    int gc = -1;
    float acc = 0.f;
    const float* H = g_bufB;
    for (int nn = n0; nn < n1; nn++) {
        int g = clampi(batch[nn], 0, G - 1);
        if (g != gc) {
            if (gc >= 0) atomicAdd(&g_gsum[gc * F + f], acc);
            acc = 0.f;
            gc = g;
        }
        acc += H[(size_t)nn * F + f];
    }
    if (gc >= 0) atomicAdd(&g_gsum[gc * F + f], acc);
}

__global__ void k_head(const float* __restrict__ linW, const float* __restrict__ linb,
                       float* __restrict__ out) {
    int t = blockIdx.x * blockDim.x + threadIdx.x;     // 640 outputs
    if (t >= G * OUTD) return;
    int g = t / OUTD;
    int o = t % OUTD;
    float c   = fmaxf((float)g_gcnt[g], 1.f);
    float inv = 1.f / c;
    float acc = 0.f;
#pragma unroll 8
    for (int h = 0; h < F; h++)
        acc = fmaf(g_gsum[g * F + h], linW[h * OUTD + o], acc);
    out[t] = acc * inv + linb[o];
}

// ---------------- launch ----------------
extern "C" void kernel_launch(void* const* d_in, const int* in_sizes, int n_in,
                              void* d_out, int out_size)
{
    // Resolve inputs BY SIZE (ordering-proof). Same-shaped tensors keep order.
    int iX = 0, iE = 0, iB = 0, iLW = 0, iLb = 0;
    int iW[3] = {0, 0, 0}, ib[3] = {0, 0, 0}, ia[2] = {0, 0};
    int nW = 0, nb = 0, na = 0;
    for (int i = 0; i < n_in; i++) {
        int s = in_sizes[i];
        if      (s == NMAX * F)   iX = i;
        else if (s == 2 * EMAX)   iE = i;
        else if (s == NMAX)       iB = i;
        else if (s == F * F)      { if (nW < 3) iW[nW++] = i; }
        else if (s == F)          { if (nb < 3) ib[nb++] = i; }
        else if (s == 1)          { if (na < 2) ia[na++] = i; }
        else if (s == F * OUTD)   iLW = i;
        else if (s == OUTD)       iLb = i;
    }

    const float* x    = (const float*)d_in[iX];
    const int*   ei   = (const int*)d_in[iE];    // int32 (JAX x64 disabled)
    const int*   bat  = (const int*)d_in[iB];
    const float* W0   = (const float*)d_in[iW[0]];
    const float* b0   = (const float*)d_in[ib[0]];
    const float* a0   = (const float*)d_in[ia[0]];
    const float* W1   = (const float*)d_in[iW[1]];
    const float* b1   = (const float*)d_in[ib[1]];
    const float* a1   = (const float*)d_in[ia[1]];
    const float* W2   = (const float*)d_in[iW[2]];
    const float* b2   = (const float*)d_in[ib[2]];
    const float* linW = (const float*)d_in[iLW];
    const float* linb = (const float*)d_in[iLb];
    float*       out  = (float*)d_out;

    int n = in_sizes[iX] / F;       // 100000
    int e = in_sizes[iE] / 2;       // 1600000
    const int* src = ei;
    const int* dst = ei + e;

    static int smem_set = 0;
    if (!smem_set) {
        cudaFuncSetAttribute(k_gemm_f16,
                             cudaFuncAttributeMaxDynamicSharedMemorySize, GEMM_SMEM);
        smem_set = 1;
    }

    int nscan       = (n + 1023) / 1024;            // 98
    int gemm_blocks = (n + 127) / 128;
    int agg_blocks  = (n * 32 + 255) / 256;         // warp per node
    int x16_blocks  = (n * 64 + 255) / 256;

    // launch index:                                                     v
    k_deg_init <<<(n + 255) / 256, 256>>>(n);                         // 0
    k_wsplit   <<<(3 * 8192 + 255) / 256, 256>>>(W0, W1, W2);         // 1
    k_x16      <<<x16_blocks, 256>>>(x, n);                           // 2
    k_gemm_f16 <<<gemm_blocks, 256, GEMM_SMEM>>>(1, 0, n);            // 3  <-- ncu slot
    k_deg_count<<<(e + 255) / 256, 256>>>(dst, e, n);                 // 4
    k_scan1    <<<nscan, 1024>>>(n);                                  // 5 (+dinv)
    k_scan2    <<<1, 128>>>(nscan, bat, n);                           // 6 (+pool_init)
    k_scan3    <<<(n + 255) / 256, 256>>>(n);                         // 7
    k_csr_fill <<<(e + 255) / 256, 256>>>(src, dst, e, n);            // 8

    k_aggregate<<<agg_blocks, 256>>>(b0, a0, n, 1);                   // 9
    k_gemm_f16 <<<gemm_blocks, 256, GEMM_SMEM>>>(0, 1, n);            // 10
    k_aggregate<<<agg_blocks, 256>>>(b1, a1, n, 1);                   // 11
    k_gemm_f16 <<<gemm_blocks, 256, GEMM_SMEM>>>(0, 2, n);            // 12
    k_aggregate<<<agg_blocks, 256>>>(b2, nullptr, n, 0);              // 13

    k_pool_sum<<<(n + 255) / 256, 128>>>(bat, n);                     // 14
    k_head<<<3, 256>>>(linW, linb, out);                              // 15
}

// round 15
// speedup vs baseline: 1.1306x; 1.1306x over previous
// R15 = R14 resubmitted verbatim (round 14 was a broker/container failure;
// the composition of the R12 aggregate + R13 pre-split-W GEMM never ran).
#include <cuda_runtime.h>
#include <cuda_bf16.h>
#include <cuda_fp16.h>
#include <math.h>
#include <stdint.h>

// Problem constants (fixed by the dataset)
#define NMAX 100000
#define EMAX 1600000
#define F    128
#define G    64
#define OUTD 10

// ---------------- device scratch (static, no allocation) ----------------
__device__ float   g_bufA[(size_t)NMAX * F];    // GEMM output h (fp32, self term)
__device__ __half2 g_bufA16[(size_t)NMAX * 64]; // GEMM output h (fp16, gathers)
__device__ float   g_bufB[(size_t)NMAX * F];    // layer output (fp32, pool/self)
__device__ __half2 g_bufB16[(size_t)NMAX * 64]; // layer output (fp16, next GEMM A)
__device__ __half2 g_x16[(size_t)NMAX * 64];    // x converted to fp16 (layer-1 A)
__device__ uint2   g_Ws[3][128 * 64];           // pre-split W: [nn][kc] {hi2,lo2}
__device__ float   g_dinv[NMAX];
__device__ int     g_deg[NMAX];                 // degree incl. self loop
__device__ int     g_scan[NMAX];
__device__ int     g_bsum[128];
__device__ int     g_rowstart[NMAX];
__device__ int     g_pos[NMAX];
__device__ float2  g_edge[EMAX];                // packed (src as int bits, norm)
__device__ float   g_gsum[G * F];
__device__ int     g_gcnt[G];

__device__ __forceinline__ int clampi(int v, int lo, int hi) {
    return v < lo ? lo : (v > hi ? hi : v);
}

__device__ __forceinline__ void mma_f16(float* c, const uint32_t* a,
                                        uint32_t b0, uint32_t b1) {
    asm volatile(
        "mma.sync.aligned.m16n8k16.row.col.f32.f16.f16.f32 "
        "{%0,%1,%2,%3},{%4,%5,%6,%7},{%8,%9},{%0,%1,%2,%3};"
        : "+f"(c[0]), "+f"(c[1]), "+f"(c[2]), "+f"(c[3])
        : "r"(a[0]), "r"(a[1]), "r"(a[2]), "r"(a[3]), "r"(b0), "r"(b1));
}

// ---------------- degree ----------------
__global__ void k_deg_init(int n) {
    int i = blockIdx.x * blockDim.x + threadIdx.x;
    if (i < n) g_deg[i] = 1;            // self loop contributes 1
}

__global__ void k_deg_count(const int* __restrict__ dst, int e, int n) {
    int i = blockIdx.x * blockDim.x + threadIdx.x;
    if (i < e) atomicAdd(&g_deg[clampi(dst[i], 0, n - 1)], 1);
}

// ---------------- W pre-split: {hi,lo} fp16 pairs, [nn][kc] layout ----------------
__global__ void k_wsplit(const float* __restrict__ W0, const float* __restrict__ W1,
                         const float* __restrict__ W2) {
    int i = blockIdx.x * blockDim.x + threadIdx.x;    // 0..24575
    if (i >= 3 * 128 * 64) return;
    int which = i / 8192;
    int j     = i & 8191;
    int kc    = j & 63;
    int nn    = j >> 6;
    const float* W = (which == 0) ? W0 : (which == 1) ? W1 : W2;
    float w0 = W[(2 * kc) * 128 + nn];
    float w1 = W[(2 * kc + 1) * 128 + nn];
    __half h0 = __float2half_rn(w0);
    __half h1 = __float2half_rn(w1);
    __half l0 = __float2half_rn(w0 - __half2float(h0));
    __half l1 = __float2half_rn(w1 - __half2float(h1));
    __half2 hp = __halves2half2(h0, h1);
    __half2 lp = __halves2half2(l0, l1);
    uint2 q;
    q.x = *(uint32_t*)&hp;
    q.y = *(uint32_t*)&lp;
    g_Ws[which][nn * 64 + kc] = q;
}

// ---------------- x -> fp16 ----------------
__global__ void k_x16(const float* __restrict__ x, int n) {
    int i = blockIdx.x * blockDim.x + threadIdx.x;   // half2 units: n*64
    if (i < n * 64) {
        float2 v = ((const float2*)x)[i];
        g_x16[i] = __float22half2_rn(v);
    }
}

// ---------------- scan1 (+dinv fused) ----------------
__global__ void k_scan1(int n) {                 // 1024 threads/block
    __shared__ int sh[1024];
    int gid = blockIdx.x * 1024 + threadIdx.x;
    int deg = (gid < n) ? g_deg[gid] : 1;
    if (gid < n) g_dinv[gid] = rsqrtf((float)deg);
    int v = (gid < n) ? (deg - 1) : 0;
    sh[threadIdx.x] = v;
    __syncthreads();
    for (int off = 1; off < 1024; off <<= 1) {   // Hillis-Steele inclusive
        int t = (threadIdx.x >= off) ? sh[threadIdx.x - off] : 0;
        __syncthreads();
        sh[threadIdx.x] += t;
        __syncthreads();
    }
    if (gid < n) g_scan[gid] = sh[threadIdx.x];
    if (threadIdx.x == 1023) g_bsum[blockIdx.x] = sh[1023];
}

// ---------------- scan2 (+pool_init fused) ----------------
__global__ void k_scan2(int nb, const int* __restrict__ batch, int n) {  // 1 block, 128 thr
    __shared__ int sh[128];
    int t = threadIdx.x;
    sh[t] = (t < nb) ? g_bsum[t] : 0;
    __syncthreads();
    if (t == 0) {
        int acc = 0;
        for (int i = 0; i < nb; i++) { int v = sh[i]; sh[i] = acc; acc += v; }
    }
    __syncthreads();
    if (t < nb) g_bsum[t] = sh[t];

    // pool init
    for (int i = t; i < G * F; i += blockDim.x) g_gsum[i] = 0.f;
    if (t < G) {
        int lo, hi;
        {
            int a = 0, b = n;
            while (a < b) { int m = (a + b) >> 1; if (batch[m] < t) a = m + 1; else b = m; }
            lo = a;
        }
        {
            int a = 0, b = n;
            while (a < b) { int m = (a + b) >> 1; if (batch[m] < t + 1) a = m + 1; else b = m; }
            hi = a;
        }
        g_gcnt[t] = hi - lo;
    }
}

__global__ void k_scan3(int n) {
    int gid = blockIdx.x * blockDim.x + threadIdx.x;
    if (gid >= n) return;
    int cnt   = g_deg[gid] - 1;
    int start = g_scan[gid] - cnt + g_bsum[gid >> 10];   // exclusive start
    g_rowstart[gid] = start;
    g_pos[gid]      = start;
}

__global__ void k_csr_fill(const int* __restrict__ src, const int* __restrict__ dst,
                           int e, int n) {
    int i = blockIdx.x * blockDim.x + threadIdx.x;
    if (i >= e) return;
    int s = clampi(src[i], 0, n - 1);
    int d = clampi(dst[i], 0, n - 1);
    int slot = atomicAdd(&g_pos[d], 1);
    g_edge[slot] = make_float2(__int_as_float(s), g_dinv[s] * g_dinv[d]);
}

// ---------------- fp16 tensor-core GEMM, W split hi+lo (2 mmas) ----------------
// g_bufA[n x 128] = X[n x 128] @ W[128 x 128]; writes fp32 + fp16 copies.
// Single K pass: full A tile (fp16) + pre-split W (copied from g_Ws) in smem.
#define GAS 68   // half2 per A row (64 + 4 pad)
#define GWS 68   // uint2 per WP row (64 + 4 pad)
#define GEMM_SMEM (128 * GAS * 4 + 128 * GWS * 8)   // 104448 B
__global__ __launch_bounds__(256, 2) void k_gemm_f16(
    int use_ext, int wsel, int nrows)
{
    extern __shared__ char sm_[];
    __half2* A2 = (__half2*)sm_;                      // [128][GAS]  A[m][k-pair]
    uint2*   WP = (uint2*)(sm_ + 128 * GAS * 4);      // [128][GWS]  {hi2,lo2} per n,kc

    const __half2* Xsrc = use_ext ? g_x16 : g_bufB16;
    const uint2*   Ws   = g_Ws[wsel];

    int tid  = threadIdx.x;
    int row0 = blockIdx.x * 128;

    // ---- fill A tile: straight fp16 copy (coalesced 16B chunks) ----
#pragma unroll
    for (int i = 0; i < 8; i++) {
        int c  = tid + i * 256;        // 0..2047 chunks of 4 half2
        int m  = c >> 4;               // 0..127
        int kq = (c & 15) * 4;         // half2 col 0,4,..60
        uint4 v = make_uint4(0u, 0u, 0u, 0u);
        int row = row0 + m;
        if (row < nrows) v = *(const uint4*)(Xsrc + (size_t)row * 64 + kq);
        *(uint4*)(A2 + m * GAS + kq) = v;
    }
    // ---- fill WP: pure uint4 copy of pre-split W ----
#pragma unroll
    for (int i = 0; i < 16; i++) {
        int f  = tid + i * 256;        // 0..4095 uint4 (2 uint2 each)
        int nn = f >> 5;               // 32 uint4 per row
        int kc = (f & 31) * 2;
        uint4 v = *(const uint4*)(Ws + nn * 64 + kc);
        *(uint4*)(WP + nn * GWS + kc) = v;
    }
    __syncthreads();

    int lane = tid & 31;
    int wid  = tid >> 5;
    int g    = lane >> 2;          // 0..7
    int t    = lane & 3;           // 0..3
    int wm   = (wid & 3) * 32;     // warp m offset
    int wn   = (wid >> 2) * 64;    // warp n offset

    float acc[2][8][4];
#pragma unroll
    for (int mi = 0; mi < 2; mi++)
#pragma unroll
        for (int ni = 0; ni < 8; ni++)
#pragma unroll
            for (int q = 0; q < 4; q++) acc[mi][ni][q] = 0.f;

#pragma unroll
    for (int kk = 0; kk < 8; kk++) {           // k16 steps over K=128
        int kb = kk * 8;                       // k-pair base
        uint32_t a[2][4];
#pragma unroll
        for (int mi = 0; mi < 2; mi++) {
            int m = wm + mi * 16;
            a[mi][0] = *(uint32_t*)&A2[(m + g)     * GAS + kb + t];
            a[mi][1] = *(uint32_t*)&A2[(m + g + 8) * GAS + kb + t];
            a[mi][2] = *(uint32_t*)&A2[(m + g)     * GAS + kb + 4 + t];
            a[mi][3] = *(uint32_t*)&A2[(m + g + 8) * GAS + kb + 4 + t];
        }
#pragma unroll
        for (int ni = 0; ni < 8; ni++) {
            int nn = wn + ni * 8 + g;
            uint2 q0 = WP[nn * GWS + kb + t];        // {b0_hi, b0_lo}
            uint2 q1 = WP[nn * GWS + kb + 4 + t];    // {b1_hi, b1_lo}
#pragma unroll
            for (int mi = 0; mi < 2; mi++) {
                mma_f16(acc[mi][ni], a[mi], q0.x, q1.x);   // A * W_hi
                mma_f16(acc[mi][ni], a[mi], q0.y, q1.y);   // A * W_lo
            }
        }
    }

    // ---- write C fragments (fp32 + fp16 copy) ----
#pragma unroll
    for (int mi = 0; mi < 2; mi++) {
#pragma unroll
        for (int ni = 0; ni < 8; ni++) {
            int col = wn + ni * 8 + t * 2;
            int r0  = row0 + wm + mi * 16 + g;
            int r1  = r0 + 8;
            float2 v0 = make_float2(acc[mi][ni][0], acc[mi][ni][1]);
            float2 v1 = make_float2(acc[mi][ni][2], acc[mi][ni][3]);
            if (r0 < nrows) {
                *(float2*)(g_bufA + (size_t)r0 * 128 + col) = v0;
                g_bufA16[(size_t)r0 * 64 + (col >> 1)] = __float22half2_rn(v0);
            }
            if (r1 < nrows) {
                *(float2*)(g_bufA + (size_t)r1 * 128 + col) = v1;
                g_bufA16[(size_t)r1 * 64 + (col >> 1)] = __float22half2_rn(v1);
            }
        }
    }
}

// ---- fused aggregate: bufB[d] = prelu(dinv2*bufA[d] + sum norm*h16[s] + bias) ----
// Warp per dst node; lane owns 4 features. Self term fp32, gathers fp16.
// R12 loop (depth-1 prefetch) — twice-verified local optimum; do not restructure.
__global__ void k_aggregate(const float* __restrict__ bias,
                            const float* __restrict__ aP, int n, int do_prelu)
{
    int gw   = (blockIdx.x * blockDim.x + threadIdx.x) >> 5;
    int lane = threadIdx.x & 31;
    if (gw >= n) return;

    int   start = g_rowstart[gw];
    int   cnt   = g_deg[gw] - 1;
    float dv    = g_dinv[gw];

    float4 acc = *((const float4*)(g_bufA + (size_t)gw * 128) + lane);
    float  sc  = dv * dv;
    acc.x *= sc; acc.y *= sc; acc.z *= sc; acc.w *= sc;

    if (cnt > 0) {
        float2 e0 = g_edge[start];
        int    s0 = __float_as_int(e0.x);
        uint2  h0 = *((const uint2*)(g_bufA16 + (size_t)s0 * 64) + lane);
        for (int k = 1; k < cnt; k++) {
            float2 e1 = g_edge[start + k];          // prefetch next edge
            int    s1 = __float_as_int(e1.x);
            uint2  h1 = *((const uint2*)(g_bufA16 + (size_t)s1 * 64) + lane);
            float2 p0 = __half22float2(*(const __half2*)&h0.x);
            float2 p1 = __half22float2(*(const __half2*)&h0.y);
            acc.x = fmaf(e0.y, p0.x, acc.x);
            acc.y = fmaf(e0.y, p0.y, acc.y);
            acc.z = fmaf(e0.y, p1.x, acc.z);
            acc.w = fmaf(e0.y, p1.y, acc.w);
            e0 = e1; h0 = h1;
        }
        float2 p0 = __half22float2(*(const __half2*)&h0.x);
        float2 p1 = __half22float2(*(const __half2*)&h0.y);
        acc.x = fmaf(e0.y, p0.x, acc.x);
        acc.y = fmaf(e0.y, p0.y, acc.y);
        acc.z = fmaf(e0.y, p1.x, acc.z);
        acc.w = fmaf(e0.y, p1.y, acc.w);
    }

    float4 b = *((const float4*)bias + lane);
    acc.x += b.x; acc.y += b.y; acc.z += b.z; acc.w += b.w;

    if (do_prelu) {
        float al = aP[0];
        acc.x = acc.x > 0.f ? acc.x : al * acc.x;
        acc.y = acc.y > 0.f ? acc.y : al * acc.y;
        acc.z = acc.z > 0.f ? acc.z : al * acc.z;
        acc.w = acc.w > 0.f ? acc.w : al * acc.w;
    }
    *((float4*)(g_bufB + (size_t)gw * 128) + lane) = acc;

    __half2 o0 = __float22half2_rn(make_float2(acc.x, acc.y));
    __half2 o1 = __float22half2_rn(make_float2(acc.z, acc.w));
    uint2 ov;
    ov.x = *(uint32_t*)&o0;
    ov.y = *(uint32_t*)&o1;
    *((uint2*)(g_bufB16 + (size_t)gw * 64) + lane) = ov;
}

// ---------------- pooling ----------------
// 128 threads per block (one per feature); each block handles 256 nodes.
__global__ void k_pool_sum(const int* __restrict__ batch, int n) {
    int f  = threadIdx.x;                      // 0..127
    int n0 = blockIdx.x * 256;
    int n1 = min(n0 + 256, n);
    int gc = -1;
    float acc = 0.f;
    const float* H = g_bufB;
    for (int nn = n0; nn < n1; nn++) {
        int g = clampi(batch[nn], 0, G - 1);
        if (g != gc) {
            if (gc >= 0) atomicAdd(&g_gsum[gc * F + f], acc);
            acc = 0.f;
            gc = g;
        }
        acc += H[(size_t)nn * F + f];
    }
    if (gc >= 0) atomicAdd(&g_gsum[gc * F + f], acc);
}

__global__ void k_head(const float* __restrict__ linW, const float* __restrict__ linb,
                       float* __restrict__ out) {
    int t = blockIdx.x * blockDim.x + threadIdx.x;     // 640 outputs
    if (t >= G * OUTD) return;
    int g = t / OUTD;
    int o = t % OUTD;
    float c   = fmaxf((float)g_gcnt[g], 1.f);
    float inv = 1.f / c;
    float acc = 0.f;
#pragma unroll 8
    for (int h = 0; h < F; h++)
        acc = fmaf(g_gsum[g * F + h], linW[h * OUTD + o], acc);
    out[t] = acc * inv + linb[o];
}

// ---------------- launch ----------------
extern "C" void kernel_launch(void* const* d_in, const int* in_sizes, int n_in,
                              void* d_out, int out_size)
{
    // Resolve inputs BY SIZE (ordering-proof). Same-shaped tensors keep order.
    int iX = 0, iE = 0, iB = 0, iLW = 0, iLb = 0;
    int iW[3] = {0, 0, 0}, ib[3] = {0, 0, 0}, ia[2] = {0, 0};
    int nW = 0, nb = 0, na = 0;
    for (int i = 0; i < n_in; i++) {
        int s = in_sizes[i];
        if      (s == NMAX * F)   iX = i;
        else if (s == 2 * EMAX)   iE = i;
        else if (s == NMAX)       iB = i;
        else if (s == F * F)      { if (nW < 3) iW[nW++] = i; }
        else if (s == F)          { if (nb < 3) ib[nb++] = i; }
        else if (s == 1)          { if (na < 2) ia[na++] = i; }
        else if (s == F * OUTD)   iLW = i;
        else if (s == OUTD)       iLb = i;
    }

    const float* x    = (const float*)d_in[iX];
    const int*   ei   = (const int*)d_in[iE];    // int32 (JAX x64 disabled)
    const int*   bat  = (const int*)d_in[iB];
    const float* W0   = (const float*)d_in[iW[0]];
    const float* b0   = (const float*)d_in[ib[0]];
    const float* a0   = (const float*)d_in[ia[0]];
    const float* W1   = (const float*)d_in[iW[1]];
    const float* b1   = (const float*)d_in[ib[1]];
    const float* a1   = (const float*)d_in[ia[1]];
    const float* W2   = (const float*)d_in[iW[2]];
    const float* b2   = (const float*)d_in[ib[2]];
    const float* linW = (const float*)d_in[iLW];
    const float* linb = (const float*)d_in[iLb];
    float*       out  = (float*)d_out;

    int n = in_sizes[iX] / F;       // 100000
    int e = in_sizes[iE] / 2;       // 1600000
    const int* src = ei;
    const int* dst = ei + e;

    static int smem_set = 0;
    if (!smem_set) {
        cudaFuncSetAttribute(k_gemm_f16,
                             cudaFuncAttributeMaxDynamicSharedMemorySize, GEMM_SMEM);
        smem_set = 1;
    }

    int nscan       = (n + 1023) / 1024;            // 98
    int gemm_blocks = (n + 127) / 128;
    int agg_blocks  = (n * 32 + 255) / 256;         // warp per node
    int x16_blocks  = (n * 64 + 255) / 256;

    // launch index:                                                     v
    k_deg_init <<<(n + 255) / 256, 256>>>(n);                         // 0
    k_wsplit   <<<(3 * 8192 + 255) / 256, 256>>>(W0, W1, W2);         // 1
    k_x16      <<<x16_blocks, 256>>>(x, n);                           // 2
    k_gemm_f16 <<<gemm_blocks, 256, GEMM_SMEM>>>(1, 0, n);            // 3  <-- ncu slot
    k_deg_count<<<(e + 255) / 256, 256>>>(dst, e, n);                 // 4
    k_scan1    <<<nscan, 1024>>>(n);                                  // 5 (+dinv)
    k_scan2    <<<1, 128>>>(nscan, bat, n);                           // 6 (+pool_init)
    k_scan3    <<<(n + 255) / 256, 256>>>(n);                         // 7
    k_csr_fill <<<(e + 255) / 256, 256>>>(src, dst, e, n);            // 8

    k_aggregate<<<agg_blocks, 256>>>(b0, a0, n, 1);                   // 9
    k_gemm_f16 <<<gemm_blocks, 256, GEMM_SMEM>>>(0, 1, n);            // 10
    k_aggregate<<<agg_blocks, 256>>>(b1, a1, n, 1);                   // 11
    k_gemm_f16 <<<gemm_blocks, 256, GEMM_SMEM>>>(0, 2, n);            // 12
    k_aggregate<<<agg_blocks, 256>>>(b2, nullptr, n, 0);              // 13

    k_pool_sum<<<(n + 255) / 256, 128>>>(bat, n);                     // 14
    k_head<<<3, 256>>>(linW, linb, out);                              // 15
}

// round 16
// speedup vs baseline: 1.3300x; 1.1763x over previous
#include <cuda_runtime.h>
#include <cuda_bf16.h>
#include <cuda_fp16.h>
#include <math.h>
#include <stdint.h>

// Problem constants (fixed by the dataset)
#define NMAX 100000
#define EMAX 1600000
#define F    128
#define G    64
#define OUTD 10

// ---------------- device scratch (static, no allocation) ----------------
__device__ __half2 g_bufA16[(size_t)NMAX * 64]; // GEMM output h (fp16)
__device__ __half2 g_bufB16[(size_t)NMAX * 64]; // layer output (fp16)
__device__ __half2 g_x16[(size_t)NMAX * 64];    // x converted to fp16 (layer-1 A)
__device__ uint2   g_Ws[3][128 * 64];           // pre-split W: [nn][kc] {hi2,lo2}
__device__ float   g_dinv[NMAX];
__device__ int     g_deg[NMAX];                 // degree incl. self loop
__device__ int     g_scan[NMAX];
__device__ int     g_bsum[128];
__device__ int     g_rowstart[NMAX];
__device__ int     g_pos[NMAX];
__device__ float2  g_edge[EMAX];                // packed (src as int bits, norm)
__device__ float   g_gsum[G * F];
__device__ int     g_gcnt[G];

__device__ __forceinline__ int clampi(int v, int lo, int hi) {
    return v < lo ? lo : (v > hi ? hi : v);
}

__device__ __forceinline__ void mma_f16(float* c, const uint32_t* a,
                                        uint32_t b0, uint32_t b1) {
    asm volatile(
        "mma.sync.aligned.m16n8k16.row.col.f32.f16.f16.f32 "
        "{%0,%1,%2,%3},{%4,%5,%6,%7},{%8,%9},{%0,%1,%2,%3};"
        : "+f"(c[0]), "+f"(c[1]), "+f"(c[2]), "+f"(c[3])
        : "r"(a[0]), "r"(a[1]), "r"(a[2]), "r"(a[3]), "r"(b0), "r"(b1));
}

// ---------------- degree ----------------
__global__ void k_deg_init(int n) {
    int i = blockIdx.x * blockDim.x + threadIdx.x;
    if (i < n) g_deg[i] = 1;            // self loop contributes 1
}

__global__ void k_deg_count(const int* __restrict__ dst, int e, int n) {
    int i = blockIdx.x * blockDim.x + threadIdx.x;
    if (i < e) atomicAdd(&g_deg[clampi(dst[i], 0, n - 1)], 1);
}

// ---------------- W pre-split: {hi,lo} fp16 pairs, [nn][kc] layout ----------------
__global__ void k_wsplit(const float* __restrict__ W0, const float* __restrict__ W1,
                         const float* __restrict__ W2) {
    int i = blockIdx.x * blockDim.x + threadIdx.x;    // 0..24575
    if (i >= 3 * 128 * 64) return;
    int which = i / 8192;
    int j     = i & 8191;
    int kc    = j & 63;
    int nn    = j >> 6;
    const float* W = (which == 0) ? W0 : (which == 1) ? W1 : W2;
    float w0 = W[(2 * kc) * 128 + nn];
    float w1 = W[(2 * kc + 1) * 128 + nn];
    __half h0 = __float2half_rn(w0);
    __half h1 = __float2half_rn(w1);
    __half l0 = __float2half_rn(w0 - __half2float(h0));
    __half l1 = __float2half_rn(w1 - __half2float(h1));
    __half2 hp = __halves2half2(h0, h1);
    __half2 lp = __halves2half2(l0, l1);
    uint2 q;
    q.x = *(uint32_t*)&hp;
    q.y = *(uint32_t*)&lp;
    g_Ws[which][nn * 64 + kc] = q;
}

// ---------------- x -> fp16 ----------------
__global__ void k_x16(const float* __restrict__ x, int n) {
    int i = blockIdx.x * blockDim.x + threadIdx.x;   // half2 units: n*64
    if (i < n * 64) {
        float2 v = ((const float2*)x)[i];
        g_x16[i] = __float22half2_rn(v);
    }
}

// ---------------- scan1 (+dinv fused) ----------------
__global__ void k_scan1(int n) {                 // 1024 threads/block
    __shared__ int sh[1024];
    int gid = blockIdx.x * 1024 + threadIdx.x;
    int deg = (gid < n) ? g_deg[gid] : 1;
    if (gid < n) g_dinv[gid] = rsqrtf((float)deg);
    int v = (gid < n) ? (deg - 1) : 0;
    sh[threadIdx.x] = v;
    __syncthreads();
    for (int off = 1; off < 1024; off <<= 1) {   // Hillis-Steele inclusive
        int t = (threadIdx.x >= off) ? sh[threadIdx.x - off] : 0;
        __syncthreads();
        sh[threadIdx.x] += t;
        __syncthreads();
    }
    if (gid < n) g_scan[gid] = sh[threadIdx.x];
    if (threadIdx.x == 1023) g_bsum[blockIdx.x] = sh[1023];
}

// ---------------- scan2 (+pool_init fused) ----------------
__global__ void k_scan2(int nb, const int* __restrict__ batch, int n) {  // 1 block, 128 thr
    __shared__ int sh[128];
    int t = threadIdx.x;
    sh[t] = (t < nb) ? g_bsum[t] : 0;
    __syncthreads();
    if (t == 0) {
        int acc = 0;
        for (int i = 0; i < nb; i++) { int v = sh[i]; sh[i] = acc; acc += v; }
    }
    __syncthreads();
    if (t < nb) g_bsum[t] = sh[t];

    // pool init
    for (int i = t; i < G * F; i += blockDim.x) g_gsum[i] = 0.f;
    if (t < G) {
        int lo, hi;
        {
            int a = 0, b = n;
            while (a < b) { int m = (a + b) >> 1; if (batch[m] < t) a = m + 1; else b = m; }
            lo = a;
        }
        {
            int a = 0, b = n;
            while (a < b) { int m = (a + b) >> 1; if (batch[m] < t + 1) a = m + 1; else b = m; }
            hi = a;
        }
        g_gcnt[t] = hi - lo;
    }
}

__global__ void k_scan3(int n) {
    int gid = blockIdx.x * blockDim.x + threadIdx.x;
    if (gid >= n) return;
    int cnt   = g_deg[gid] - 1;
    int start = g_scan[gid] - cnt + g_bsum[gid >> 10];   // exclusive start
    g_rowstart[gid] = start;
    g_pos[gid]      = start;
}

__global__ void k_csr_fill(const int* __restrict__ src, const int* __restrict__ dst,
                           int e, int n) {
    int i = blockIdx.x * blockDim.x + threadIdx.x;
    if (i >= e) return;
    int s = clampi(src[i], 0, n - 1);
    int d = clampi(dst[i], 0, n - 1);
    int slot = atomicAdd(&g_pos[d], 1);
    g_edge[slot] = make_float2(__int_as_float(s), g_dinv[s] * g_dinv[d]);
}

// ---------------- fp16 tensor-core GEMM, W split hi+lo (2 mmas) ----------------
// g_bufA16[n x 128] = X[n x 128] @ W[128 x 128] (fp16 output only).
// Single K pass: full A tile (fp16) + pre-split W (copied from g_Ws) in smem.
#define GAS 68   // half2 per A row (64 + 4 pad)
#define GWS 68   // uint2 per WP row (64 + 4 pad)
#define GEMM_SMEM (128 * GAS * 4 + 128 * GWS * 8)   // 104448 B
__global__ __launch_bounds__(256, 2) void k_gemm_f16(
    int use_ext, int wsel, int nrows)
{
    extern __shared__ char sm_[];
    __half2* A2 = (__half2*)sm_;                      // [128][GAS]  A[m][k-pair]
    uint2*   WP = (uint2*)(sm_ + 128 * GAS * 4);      // [128][GWS]  {hi2,lo2} per n,kc

    const __half2* Xsrc = use_ext ? g_x16 : g_bufB16;
    const uint2*   Ws   = g_Ws[wsel];

    int tid  = threadIdx.x;
    int row0 = blockIdx.x * 128;

    // ---- fill A tile: straight fp16 copy (coalesced 16B chunks) ----
#pragma unroll
    for (int i = 0; i < 8; i++) {
        int c  = tid + i * 256;        // 0..2047 chunks of 4 half2
        int m  = c >> 4;               // 0..127
        int kq = (c & 15) * 4;         // half2 col 0,4,..60
        uint4 v = make_uint4(0u, 0u, 0u, 0u);
        int row = row0 + m;
        if (row < nrows) v = *(const uint4*)(Xsrc + (size_t)row * 64 + kq);
        *(uint4*)(A2 + m * GAS + kq) = v;
    }
    // ---- fill WP: pure uint4 copy of pre-split W ----
#pragma unroll
    for (int i = 0; i < 16; i++) {
        int f  = tid + i * 256;        // 0..4095 uint4 (2 uint2 each)
        int nn = f >> 5;               // 32 uint4 per row
        int kc = (f & 31) * 2;
        uint4 v = *(const uint4*)(Ws + nn * 64 + kc);
        *(uint4*)(WP + nn * GWS + kc) = v;
    }
    __syncthreads();

    int lane = tid & 31;
    int wid  = tid >> 5;
    int g    = lane >> 2;          // 0..7
    int t    = lane & 3;           // 0..3
    int wm   = (wid & 3) * 32;     // warp m offset
    int wn   = (wid >> 2) * 64;    // warp n offset

    float acc[2][8][4];
#pragma unroll
    for (int mi = 0; mi < 2; mi++)
#pragma unroll
        for (int ni = 0; ni < 8; ni++)
#pragma unroll
            for (int q = 0; q < 4; q++) acc[mi][ni][q] = 0.f;

#pragma unroll
    for (int kk = 0; kk < 8; kk++) {           // k16 steps over K=128
        int kb = kk * 8;                       // k-pair base
        uint32_t a[2][4];
#pragma unroll
        for (int mi = 0; mi < 2; mi++) {
            int m = wm + mi * 16;
            a[mi][0] = *(uint32_t*)&A2[(m + g)     * GAS + kb + t];
            a[mi][1] = *(uint32_t*)&A2[(m + g + 8) * GAS + kb + t];
            a[mi][2] = *(uint32_t*)&A2[(m + g)     * GAS + kb + 4 + t];
            a[mi][3] = *(uint32_t*)&A2[(m + g + 8) * GAS + kb + 4 + t];
        }
#pragma unroll
        for (int ni = 0; ni < 8; ni++) {
            int nn = wn + ni * 8 + g;
            uint2 q0 = WP[nn * GWS + kb + t];        // {b0_hi, b0_lo}
            uint2 q1 = WP[nn * GWS + kb + 4 + t];    // {b1_hi, b1_lo}
#pragma unroll
            for (int mi = 0; mi < 2; mi++) {
                mma_f16(acc[mi][ni], a[mi], q0.x, q1.x);   // A * W_hi
                mma_f16(acc[mi][ni], a[mi], q0.y, q1.y);   // A * W_lo
            }
        }
    }

    // ---- write C fragments (fp16 only) ----
#pragma unroll
    for (int mi = 0; mi < 2; mi++) {
#pragma unroll
        for (int ni = 0; ni < 8; ni++) {
            int col = wn + ni * 8 + t * 2;          // even
            int r0  = row0 + wm + mi * 16 + g;
            int r1  = r0 + 8;
            if (r0 < nrows)
                g_bufA16[(size_t)r0 * 64 + (col >> 1)] =
                    __float22half2_rn(make_float2(acc[mi][ni][0], acc[mi][ni][1]));
            if (r1 < nrows)
                g_bufA16[(size_t)r1 * 64 + (col >> 1)] =
                    __float22half2_rn(make_float2(acc[mi][ni][2], acc[mi][ni][3]));
        }
    }
}

// ---- fused aggregate: B16[d] = prelu(dinv2*A16[d] + sum norm*A16[s] + bias) ----
// Warp per dst node; lane owns 4 features. fp32 accumulate, fp16 in/out.
// R12 loop (depth-1 prefetch) — twice-verified local optimum; do not restructure.
__global__ void k_aggregate(const float* __restrict__ bias,
                            const float* __restrict__ aP, int n, int do_prelu)
{
    int gw   = (blockIdx.x * blockDim.x + threadIdx.x) >> 5;
    int lane = threadIdx.x & 31;
    if (gw >= n) return;

    int   start = g_rowstart[gw];
    int   cnt   = g_deg[gw] - 1;
    float dv    = g_dinv[gw];

    // self term from fp16
    uint2  hs = *((const uint2*)(g_bufA16 + (size_t)gw * 64) + lane);
    float2 s0 = __half22float2(*(const __half2*)&hs.x);
    float2 s1 = __half22float2(*(const __half2*)&hs.y);
    float  sc = dv * dv;
    float4 acc = make_float4(s0.x * sc, s0.y * sc, s1.x * sc, s1.y * sc);

    if (cnt > 0) {
        float2 e0 = g_edge[start];
        int    sI = __float_as_int(e0.x);
        uint2  h0 = *((const uint2*)(g_bufA16 + (size_t)sI * 64) + lane);
        for (int k = 1; k < cnt; k++) {
            float2 e1 = g_edge[start + k];          // prefetch next edge
            int    s1i = __float_as_int(e1.x);
            uint2  h1 = *((const uint2*)(g_bufA16 + (size_t)s1i * 64) + lane);
            float2 p0 = __half22float2(*(const __half2*)&h0.x);
            float2 p1 = __half22float2(*(const __half2*)&h0.y);
            acc.x = fmaf(e0.y, p0.x, acc.x);
            acc.y = fmaf(e0.y, p0.y, acc.y);
            acc.z = fmaf(e0.y, p1.x, acc.z);
            acc.w = fmaf(e0.y, p1.y, acc.w);
            e0 = e1; h0 = h1;
        }
        float2 p0 = __half22float2(*(const __half2*)&h0.x);
        float2 p1 = __half22float2(*(const __half2*)&h0.y);
        acc.x = fmaf(e0.y, p0.x, acc.x);
        acc.y = fmaf(e0.y, p0.y, acc.y);
        acc.z = fmaf(e0.y, p1.x, acc.z);
        acc.w = fmaf(e0.y, p1.y, acc.w);
    }

    float4 b = *((const float4*)bias + lane);
    acc.x += b.x; acc.y += b.y; acc.z += b.z; acc.w += b.w;

    if (do_prelu) {
        float al = aP[0];
        acc.x = acc.x > 0.f ? acc.x : al * acc.x;
        acc.y = acc.y > 0.f ? acc.y : al * acc.y;
        acc.z = acc.z > 0.f ? acc.z : al * acc.z;
        acc.w = acc.w > 0.f ? acc.w : al * acc.w;
    }

    __half2 o0 = __float22half2_rn(make_float2(acc.x, acc.y));
    __half2 o1 = __float22half2_rn(make_float2(acc.z, acc.w));
    uint2 ov;
    ov.x = *(uint32_t*)&o0;
    ov.y = *(uint32_t*)&o1;
    *((uint2*)(g_bufB16 + (size_t)gw * 64) + lane) = ov;
}

// ---------------- pooling (reads fp16, accumulates fp32) ----------------
// 128 threads per block (one per feature); each block handles 256 nodes.
__global__ void k_pool_sum(const int* __restrict__ batch, int n) {
    int f  = threadIdx.x;                      // 0..127
    int n0 = blockIdx.x * 256;
    int n1 = min(n0 + 256, n);
    int gc = -1;
    float acc = 0.f;
    const __half* H = (const __half*)g_bufB16;
    for (int nn = n0; nn < n1; nn++) {
        int g = clampi(batch[nn], 0, G - 1);
        if (g != gc) {
            if (gc >= 0) atomicAdd(&g_gsum[gc * F + f], acc);
            acc = 0.f;
            gc = g;
        }
        acc += __half2float(H[(size_t)nn * F + f]);
    }
    if (gc >= 0) atomicAdd(&g_gsum[gc * F + f], acc);
}

__global__ void k_head(const float* __restrict__ linW, const float* __restrict__ linb,
                       float* __restrict__ out) {
    int t = blockIdx.x * blockDim.x + threadIdx.x;     // 640 outputs
    if (t >= G * OUTD) return;
    int g = t / OUTD;
    int o = t % OUTD;
    float c   = fmaxf((float)g_gcnt[g], 1.f);
    float inv = 1.f / c;
    float acc = 0.f;
#pragma unroll 8
    for (int h = 0; h < F; h++)
        acc = fmaf(g_gsum[g * F + h], linW[h * OUTD + o], acc);
    out[t] = acc * inv + linb[o];
}

// ---------------- launch ----------------
extern "C" void kernel_launch(void* const* d_in, const int* in_sizes, int n_in,
                              void* d_out, int out_size)
{
    // Resolve inputs BY SIZE (ordering-proof). Same-shaped tensors keep order.
    int iX = 0, iE = 0, iB = 0, iLW = 0, iLb = 0;
    int iW[3] = {0, 0, 0}, ib[3] = {0, 0, 0}, ia[2] = {0, 0};
    int nW = 0, nb = 0, na = 0;
    for (int i = 0; i < n_in; i++) {
        int s = in_sizes[i];
        if      (s == NMAX * F)   iX = i;
        else if (s == 2 * EMAX)   iE = i;
        else if (s == NMAX)       iB = i;
        else if (s == F * F)      { if (nW < 3) iW[nW++] = i; }
        else if (s == F)          { if (nb < 3) ib[nb++] = i; }
        else if (s == 1)          { if (na < 2) ia[na++] = i; }
        else if (s == F * OUTD)   iLW = i;
        else if (s == OUTD)       iLb = i;
    }

    const float* x    = (const float*)d_in[iX];
    const int*   ei   = (const int*)d_in[iE];    // int32 (JAX x64 disabled)
    const int*   bat  = (const int*)d_in[iB];
    const float* W0   = (const float*)d_in[iW[0]];
    const float* b0   = (const float*)d_in[ib[0]];
    const float* a0   = (const float*)d_in[ia[0]];
    const float* W1   = (const float*)d_in[iW[1]];
    const float* b1   = (const float*)d_in[ib[1]];
    const float* a1   = (const float*)d_in[ia[1]];
    const float* W2   = (const float*)d_in[iW[2]];
    const float* b2   = (const float*)d_in[ib[2]];
    const float* linW = (const float*)d_in[iLW];
    const float* linb = (const float*)d_in[iLb];
    float*       out  = (float*)d_out;

    int n = in_sizes[iX] / F;       // 100000
    int e = in_sizes[iE] / 2;       // 1600000
    const int* src = ei;
    const int* dst = ei + e;

    static int smem_set = 0;
    if (!smem_set) {
        cudaFuncSetAttribute(k_gemm_f16,
                             cudaFuncAttributeMaxDynamicSharedMemorySize, GEMM_SMEM);
        smem_set = 1;
    }

    int nscan       = (n + 1023) / 1024;            // 98
    int gemm_blocks = (n + 127) / 128;
    int agg_blocks  = (n * 32 + 255) / 256;         // warp per node
    int x16_blocks  = (n * 64 + 255) / 256;

    // launch index:                                                     v
    k_deg_init <<<(n + 255) / 256, 256>>>(n);                         // 0
    k_wsplit   <<<(3 * 8192 + 255) / 256, 256>>>(W0, W1, W2);         // 1
    k_x16      <<<x16_blocks, 256>>>(x, n);                           // 2
    k_gemm_f16 <<<gemm_blocks, 256, GEMM_SMEM>>>(1, 0, n);            // 3  <-- ncu slot
    k_deg_count<<<(e + 255) / 256, 256>>>(dst, e, n);                 // 4
    k_scan1    <<<nscan, 1024>>>(n);                                  // 5 (+dinv)
    k_scan2    <<<1, 128>>>(nscan, bat, n);                           // 6 (+pool_init)
    k_scan3    <<<(n + 255) / 256, 256>>>(n);                         // 7
    k_csr_fill <<<(e + 255) / 256, 256>>>(src, dst, e, n);            // 8

    k_aggregate<<<agg_blocks, 256>>>(b0, a0, n, 1);                   // 9
    k_gemm_f16 <<<gemm_blocks, 256, GEMM_SMEM>>>(0, 1, n);            // 10
    k_aggregate<<<agg_blocks, 256>>>(b1, a1, n, 1);                   // 11
    k_gemm_f16 <<<gemm_blocks, 256, GEMM_SMEM>>>(0, 2, n);            // 12
    k_aggregate<<<agg_blocks, 256>>>(b2, nullptr, n, 0);              // 13

    k_pool_sum<<<(n + 255) / 256, 128>>>(bat, n);                     // 14
    k_head<<<3, 256>>>(linW, linb, out);                              // 15
}

// round 17
// speedup vs baseline: 1.3994x; 1.0522x over previous
#include <cuda_runtime.h>
#include <cuda_bf16.h>
#include <cuda_fp16.h>
#include <math.h>
#include <stdint.h>

// Problem constants (fixed by the dataset)
#define NMAX 100000
#define EMAX 1600000
#define F    128
#define G    64
#define OUTD 10

// ---------------- device scratch (static, no allocation) ----------------
__device__ __half2 g_bufA16[(size_t)NMAX * 64]; // GEMM output h (fp16)
__device__ __half2 g_bufB16[(size_t)NMAX * 64]; // layer output (fp16)
__device__ uint2   g_Ws[3][128 * 64];           // pre-split W: [nn][kc] {hi2,lo2}
__device__ float   g_dinv[NMAX];
__device__ int     g_deg[NMAX];                 // degree incl. self loop
__device__ int     g_scan[NMAX];
__device__ int     g_bsum[128];
__device__ int     g_rowstart[NMAX];
__device__ int     g_pos[NMAX];
__device__ float2  g_edge[EMAX];                // packed (src as int bits, norm)
__device__ float   g_gsum[G * F];
__device__ int     g_gcnt[G];

__device__ __forceinline__ int clampi(int v, int lo, int hi) {
    return v < lo ? lo : (v > hi ? hi : v);
}

__device__ __forceinline__ void mma_f16(float* c, const uint32_t* a,
                                        uint32_t b0, uint32_t b1) {
    asm volatile(
        "mma.sync.aligned.m16n8k16.row.col.f32.f16.f16.f32 "
        "{%0,%1,%2,%3},{%4,%5,%6,%7},{%8,%9},{%0,%1,%2,%3};"
        : "+f"(c[0]), "+f"(c[1]), "+f"(c[2]), "+f"(c[3])
        : "r"(a[0]), "r"(a[1]), "r"(a[2]), "r"(a[3]), "r"(b0), "r"(b1));
}

// ---------------- degree ----------------
__global__ void k_deg_init(int n) {
    int i = blockIdx.x * blockDim.x + threadIdx.x;
    if (i < n) g_deg[i] = 1;            // self loop contributes 1
}

// 4 edges per thread (int4 loads). e is divisible by 4 (1.6M).
__global__ void k_deg_count(const int4* __restrict__ dst4, int e4, int n) {
    int i = blockIdx.x * blockDim.x + threadIdx.x;
    if (i >= e4) return;
    int4 d = dst4[i];
    atomicAdd(&g_deg[clampi(d.x, 0, n - 1)], 1);
    atomicAdd(&g_deg[clampi(d.y, 0, n - 1)], 1);
    atomicAdd(&g_deg[clampi(d.z, 0, n - 1)], 1);
    atomicAdd(&g_deg[clampi(d.w, 0, n - 1)], 1);
}

// ---------------- W pre-split: {hi,lo} fp16 pairs, [nn][kc] layout ----------------
__global__ void k_wsplit(const float* __restrict__ W0, const float* __restrict__ W1,
                         const float* __restrict__ W2) {
    int i = blockIdx.x * blockDim.x + threadIdx.x;    // 0..24575
    if (i >= 3 * 128 * 64) return;
    int which = i / 8192;
    int j     = i & 8191;
    int kc    = j & 63;
    int nn    = j >> 6;
    const float* W = (which == 0) ? W0 : (which == 1) ? W1 : W2;
    float w0 = W[(2 * kc) * 128 + nn];
    float w1 = W[(2 * kc + 1) * 128 + nn];
    __half h0 = __float2half_rn(w0);
    __half h1 = __float2half_rn(w1);
    __half l0 = __float2half_rn(w0 - __half2float(h0));
    __half l1 = __float2half_rn(w1 - __half2float(h1));
    __half2 hp = __halves2half2(h0, h1);
    __half2 lp = __halves2half2(l0, l1);
    uint2 q;
    q.x = *(uint32_t*)&hp;
    q.y = *(uint32_t*)&lp;
    g_Ws[which][nn * 64 + kc] = q;
}

// ---------------- scan1 (+dinv fused) ----------------
__global__ void k_scan1(int n) {                 // 1024 threads/block
    __shared__ int sh[1024];
    int gid = blockIdx.x * 1024 + threadIdx.x;
    int deg = (gid < n) ? g_deg[gid] : 1;
    if (gid < n) g_dinv[gid] = rsqrtf((float)deg);
    int v = (gid < n) ? (deg - 1) : 0;
    sh[threadIdx.x] = v;
    __syncthreads();
    for (int off = 1; off < 1024; off <<= 1) {   // Hillis-Steele inclusive
        int t = (threadIdx.x >= off) ? sh[threadIdx.x - off] : 0;
        __syncthreads();
        sh[threadIdx.x] += t;
        __syncthreads();
    }
    if (gid < n) g_scan[gid] = sh[threadIdx.x];
    if (threadIdx.x == 1023) g_bsum[blockIdx.x] = sh[1023];
}

// ---------------- scan2 (+pool_init fused) ----------------
__global__ void k_scan2(int nb, const int* __restrict__ batch, int n) {  // 1 block, 128 thr
    __shared__ int sh[128];
    int t = threadIdx.x;
    sh[t] = (t < nb) ? g_bsum[t] : 0;
    __syncthreads();
    if (t == 0) {
        int acc = 0;
        for (int i = 0; i < nb; i++) { int v = sh[i]; sh[i] = acc; acc += v; }
    }
    __syncthreads();
    if (t < nb) g_bsum[t] = sh[t];

    // pool init
    for (int i = t; i < G * F; i += blockDim.x) g_gsum[i] = 0.f;
    if (t < G) {
        int lo, hi;
        {
            int a = 0, b = n;
            while (a < b) { int m = (a + b) >> 1; if (batch[m] < t) a = m + 1; else b = m; }
            lo = a;
        }
        {
            int a = 0, b = n;
            while (a < b) { int m = (a + b) >> 1; if (batch[m] < t + 1) a = m + 1; else b = m; }
            hi = a;
        }
        g_gcnt[t] = hi - lo;
    }
}

__global__ void k_scan3(int n) {
    int gid = blockIdx.x * blockDim.x + threadIdx.x;
    if (gid >= n) return;
    int cnt   = g_deg[gid] - 1;
    int start = g_scan[gid] - cnt + g_bsum[gid >> 10];   // exclusive start
    g_rowstart[gid] = start;
    g_pos[gid]      = start;
}

// 4 edges per thread (int4 loads).
__global__ void k_csr_fill(const int4* __restrict__ src4, const int4* __restrict__ dst4,
                           int e4, int n) {
    int i = blockIdx.x * blockDim.x + threadIdx.x;
    if (i >= e4) return;
    int4 sv = src4[i];
    int4 dv = dst4[i];
    int ss[4] = {clampi(sv.x, 0, n - 1), clampi(sv.y, 0, n - 1),
                 clampi(sv.z, 0, n - 1), clampi(sv.w, 0, n - 1)};
    int dd[4] = {clampi(dv.x, 0, n - 1), clampi(dv.y, 0, n - 1),
                 clampi(dv.z, 0, n - 1), clampi(dv.w, 0, n - 1)};
#pragma unroll
    for (int k = 0; k < 4; k++) {
        int slot = atomicAdd(&g_pos[dd[k]], 1);
        g_edge[slot] = make_float2(__int_as_float(ss[k]), g_dinv[ss[k]] * g_dinv[dd[k]]);
    }
}

// ---------------- fp16 tensor-core GEMM, W split hi+lo (2 mmas) ----------------
// g_bufA16[n x 128] = X[n x 128] @ W[128 x 128] (fp16 output only).
// Block: 512 threads (16 warps), 256 rows; warp tile 32x64; 1 block/SM.
// Single K pass: A tile (256x128 fp16) + pre-split W in smem.
// Layer 1 converts fp32 x in the fill (k_x16 fused).
#define GAS 68   // half2 per A row (64 + 4 pad)
#define GWS 68   // uint2 per WP row (64 + 4 pad)
#define GEMM_SMEM (256 * GAS * 4 + 128 * GWS * 8)   // 69632 + 69632 = 139264 B
__global__ __launch_bounds__(512, 1) void k_gemm_f16(
    const float* __restrict__ Xf, int use_ext, int wsel, int nrows)
{
    extern __shared__ char sm_[];
    __half2* A2 = (__half2*)sm_;                      // [256][GAS]  A[m][k-pair]
    uint2*   WP = (uint2*)(sm_ + 256 * GAS * 4);      // [128][GWS]  {hi2,lo2} per n,kc

    const uint2* Ws = g_Ws[wsel];

    int tid  = threadIdx.x;
    int row0 = blockIdx.x * 256;

    // ---- fill A tile: 4096 chunks of 4 half2 (16B) ----
#pragma unroll
    for (int i = 0; i < 8; i++) {
        int c  = tid + i * 512;        // 0..4095
        int m  = c >> 4;               // 0..255
        int kq = (c & 15) * 4;         // half2 col 0,4,..60
        int row = row0 + m;
        uint4 v = make_uint4(0u, 0u, 0u, 0u);
        if (row < nrows) {
            if (use_ext) {
                const float4* xs = (const float4*)(Xf + (size_t)row * 128 + kq * 2);
                float4 u0 = xs[0];
                float4 u1 = xs[1];
                __half2 h0 = __float22half2_rn(make_float2(u0.x, u0.y));
                __half2 h1 = __float22half2_rn(make_float2(u0.z, u0.w));
                __half2 h2 = __float22half2_rn(make_float2(u1.x, u1.y));
                __half2 h3 = __float22half2_rn(make_float2(u1.z, u1.w));
                v.x = *(uint32_t*)&h0; v.y = *(uint32_t*)&h1;
                v.z = *(uint32_t*)&h2; v.w = *(uint32_t*)&h3;
            } else {
                v = *(const uint4*)(g_bufB16 + (size_t)row * 64 + kq);
            }
        }
        *(uint4*)(A2 + m * GAS + kq) = v;
    }
    // ---- fill WP: pure uint4 copy of pre-split W (4096 uint4) ----
#pragma unroll
    for (int i = 0; i < 8; i++) {
        int f  = tid + i * 512;        // 0..4095 uint4 (2 uint2 each)
        int nn = f >> 5;               // 32 uint4 per row
        int kc = (f & 31) * 2;
        uint4 v = *(const uint4*)(Ws + nn * 64 + kc);
        *(uint4*)(WP + nn * GWS + kc) = v;
    }
    __syncthreads();

    int lane = tid & 31;
    int wid  = tid >> 5;
    int g    = lane >> 2;          // 0..7
    int t    = lane & 3;           // 0..3
    int wm   = (wid & 7) * 32;     // warp m offset: 0..224
    int wn   = (wid >> 3) * 64;    // warp n offset: 0,64

    float acc[2][8][4];
#pragma unroll
    for (int mi = 0; mi < 2; mi++)
#pragma unroll
        for (int ni = 0; ni < 8; ni++)
#pragma unroll
            for (int q = 0; q < 4; q++) acc[mi][ni][q] = 0.f;

#pragma unroll
    for (int kk = 0; kk < 8; kk++) {           // k16 steps over K=128
        int kb = kk * 8;                       // k-pair base
        uint32_t a[2][4];
#pragma unroll
        for (int mi = 0; mi < 2; mi++) {
            int m = wm + mi * 16;
            a[mi][0] = *(uint32_t*)&A2[(m + g)     * GAS + kb + t];
            a[mi][1] = *(uint32_t*)&A2[(m + g + 8) * GAS + kb + t];
            a[mi][2] = *(uint32_t*)&A2[(m + g)     * GAS + kb + 4 + t];
            a[mi][3] = *(uint32_t*)&A2[(m + g + 8) * GAS + kb + 4 + t];
        }
#pragma unroll
        for (int ni = 0; ni < 8; ni++) {
            int nn = wn + ni * 8 + g;
            uint2 q0 = WP[nn * GWS + kb + t];        // {b0_hi, b0_lo}
            uint2 q1 = WP[nn * GWS + kb + 4 + t];    // {b1_hi, b1_lo}
#pragma unroll
            for (int mi = 0; mi < 2; mi++) {
                mma_f16(acc[mi][ni], a[mi], q0.x, q1.x);   // A * W_hi
                mma_f16(acc[mi][ni], a[mi], q0.y, q1.y);   // A * W_lo
            }
        }
    }

    // ---- write C fragments (fp16 only) ----
#pragma unroll
    for (int mi = 0; mi < 2; mi++) {
#pragma unroll
        for (int ni = 0; ni < 8; ni++) {
            int col = wn + ni * 8 + t * 2;          // even
            int r0  = row0 + wm + mi * 16 + g;
            int r1  = r0 + 8;
            if (r0 < nrows)
                g_bufA16[(size_t)r0 * 64 + (col >> 1)] =
                    __float22half2_rn(make_float2(acc[mi][ni][0], acc[mi][ni][1]));
            if (r1 < nrows)
                g_bufA16[(size_t)r1 * 64 + (col >> 1)] =
                    __float22half2_rn(make_float2(acc[mi][ni][2], acc[mi][ni][3]));
        }
    }
}

// ---- fused aggregate: B16[d] = prelu(dinv2*A16[d] + sum norm*A16[s] + bias) ----
// Warp per dst node; lane owns 4 features. fp32 accumulate, fp16 in/out.
// R12 loop (depth-1 prefetch) — twice-verified local optimum; do not restructure.
__global__ void k_aggregate(const float* __restrict__ bias,
                            const float* __restrict__ aP, int n, int do_prelu)
{
    int gw   = (blockIdx.x * blockDim.x + threadIdx.x) >> 5;
    int lane = threadIdx.x & 31;
    if (gw >= n) return;

    int   start = g_rowstart[gw];
    int   cnt   = g_deg[gw] - 1;
    float dv    = g_dinv[gw];

    // self term from fp16
    uint2  hs = *((const uint2*)(g_bufA16 + (size_t)gw * 64) + lane);
    float2 s0 = __half22float2(*(const __half2*)&hs.x);
    float2 s1 = __half22float2(*(const __half2*)&hs.y);
    float  sc = dv * dv;
    float4 acc = make_float4(s0.x * sc, s0.y * sc, s1.x * sc, s1.y * sc);

    if (cnt > 0) {
        float2 e0 = g_edge[start];
        int    sI = __float_as_int(e0.x);
        uint2  h0 = *((const uint2*)(g_bufA16 + (size_t)sI * 64) + lane);
        for (int k = 1; k < cnt; k++) {
            float2 e1 = g_edge[start + k];          // prefetch next edge
            int    s1i = __float_as_int(e1.x);
            uint2  h1 = *((const uint2*)(g_bufA16 + (size_t)s1i * 64) + lane);
            float2 p0 = __half22float2(*(const __half2*)&h0.x);
            float2 p1 = __half22float2(*(const __half2*)&h0.y);
            acc.x = fmaf(e0.y, p0.x, acc.x);
            acc.y = fmaf(e0.y, p0.y, acc.y);
            acc.z = fmaf(e0.y, p1.x, acc.z);
            acc.w = fmaf(e0.y, p1.y, acc.w);
            e0 = e1; h0 = h1;
        }
        float2 p0 = __half22float2(*(const __half2*)&h0.x);
        float2 p1 = __half22float2(*(const __half2*)&h0.y);
        acc.x = fmaf(e0.y, p0.x, acc.x);
        acc.y = fmaf(e0.y, p0.y, acc.y);
        acc.z = fmaf(e0.y, p1.x, acc.z);
        acc.w = fmaf(e0.y, p1.y, acc.w);
    }

    float4 b = *((const float4*)bias + lane);
    acc.x += b.x; acc.y += b.y; acc.z += b.z; acc.w += b.w;

    if (do_prelu) {
        float al = aP[0];
        acc.x = acc.x > 0.f ? acc.x : al * acc.x;
        acc.y = acc.y > 0.f ? acc.y : al * acc.y;
        acc.z = acc.z > 0.f ? acc.z : al * acc.z;
        acc.w = acc.w > 0.f ? acc.w : al * acc.w;
    }

    __half2 o0 = __float22half2_rn(make_float2(acc.x, acc.y));
    __half2 o1 = __float22half2_rn(make_float2(acc.z, acc.w));
    uint2 ov;
    ov.x = *(uint32_t*)&o0;
    ov.y = *(uint32_t*)&o1;
    *((uint2*)(g_bufB16 + (size_t)gw * 64) + lane) = ov;
}

// ---------------- pooling (reads fp16, accumulates fp32) ----------------
// 128 threads per block (one per feature); each block handles 256 nodes.
__global__ void k_pool_sum(const int* __restrict__ batch, int n) {
    int f  = threadIdx.x;                      // 0..127
    int n0 = blockIdx.x * 256;
    int n1 = min(n0 + 256, n);
    int gc = -1;
    float acc = 0.f;
    const __half* H = (const __half*)g_bufB16;
    for (int nn = n0; nn < n1; nn++) {
        int g = clampi(batch[nn], 0, G - 1);
        if (g != gc) {
            if (gc >= 0) atomicAdd(&g_gsum[gc * F + f], acc);
            acc = 0.f;
            gc = g;
        }
        acc += __half2float(H[(size_t)nn * F + f]);
    }
    if (gc >= 0) atomicAdd(&g_gsum[gc * F + f], acc);
}

__global__ void k_head(const float* __restrict__ linW, const float* __restrict__ linb,
                       float* __restrict__ out) {
    int t = blockIdx.x * blockDim.x + threadIdx.x;     // 640 outputs
    if (t >= G * OUTD) return;
    int g = t / OUTD;
    int o = t % OUTD;
    float c   = fmaxf((float)g_gcnt[g], 1.f);
    float inv = 1.f / c;
    float acc = 0.f;
#pragma unroll 8
    for (int h = 0; h < F; h++)
        acc = fmaf(g_gsum[g * F + h], linW[h * OUTD + o], acc);
    out[t] = acc * inv + linb[o];
}

// ---------------- launch ----------------
extern "C" void kernel_launch(void* const* d_in, const int* in_sizes, int n_in,
                              void* d_out, int out_size)
{
    // Resolve inputs BY SIZE (ordering-proof). Same-shaped tensors keep order.
    int iX = 0, iE = 0, iB = 0, iLW = 0, iLb = 0;
    int iW[3] = {0, 0, 0}, ib[3] = {0, 0, 0}, ia[2] = {0, 0};
    int nW = 0, nb = 0, na = 0;
    for (int i = 0; i < n_in; i++) {
        int s = in_sizes[i];
        if      (s == NMAX * F)   iX = i;
        else if (s == 2 * EMAX)   iE = i;
        else if (s == NMAX)       iB = i;
        else if (s == F * F)      { if (nW < 3) iW[nW++] = i; }
        else if (s == F)          { if (nb < 3) ib[nb++] = i; }
        else if (s == 1)          { if (na < 2) ia[na++] = i; }
        else if (s == F * OUTD)   iLW = i;
        else if (s == OUTD)       iLb = i;
    }

    const float* x    = (const float*)d_in[iX];
    const int*   ei   = (const int*)d_in[iE];    // int32 (JAX x64 disabled)
    const int*   bat  = (const int*)d_in[iB];
    const float* W0   = (const float*)d_in[iW[0]];
    const float* b0   = (const float*)d_in[ib[0]];
    const float* a0   = (const float*)d_in[ia[0]];
    const float* W1   = (const float*)d_in[iW[1]];
    const float* b1   = (const float*)d_in[ib[1]];
    const float* a1   = (const float*)d_in[ia[1]];
    const float* W2   = (const float*)d_in[iW[2]];
    const float* b2   = (const float*)d_in[ib[2]];
    const float* linW = (const float*)d_in[iLW];
    const float* linb = (const float*)d_in[iLb];
    float*       out  = (float*)d_out;

    int n = in_sizes[iX] / F;       // 100000
    int e = in_sizes[iE] / 2;       // 1600000
    const int* src = ei;
    const int* dst = ei + e;
    int e4 = e / 4;                 // divisible (1.6M)

    static int smem_set = 0;
    if (!smem_set) {
        cudaFuncSetAttribute(k_gemm_f16,
                             cudaFuncAttributeMaxDynamicSharedMemorySize, GEMM_SMEM);
        smem_set = 1;
    }

    int nscan       = (n + 1023) / 1024;            // 98
    int gemm_blocks = (n + 255) / 256;              // 391
    int agg_blocks  = (n * 32 + 255) / 256;         // warp per node

    // launch index:                                                     v
    k_deg_init <<<(n + 255) / 256, 256>>>(n);                         // 0
    k_wsplit   <<<(3 * 8192 + 255) / 256, 256>>>(W0, W1, W2);         // 1
    k_deg_count<<<(e4 + 255) / 256, 256>>>((const int4*)dst, e4, n);  // 2
    k_gemm_f16 <<<gemm_blocks, 512, GEMM_SMEM>>>(x, 1, 0, n);         // 3  <-- ncu slot
    k_scan1    <<<nscan, 1024>>>(n);                                  // 4 (+dinv)
    k_scan2    <<<1, 128>>>(nscan, bat, n);                           // 5 (+pool_init)
    k_scan3    <<<(n + 255) / 256, 256>>>(n);                         // 6
    k_csr_fill <<<(e4 + 255) / 256, 256>>>((const int4*)src,
                                           (const int4*)dst, e4, n);  // 7

    k_aggregate<<<agg_blocks, 256>>>(b0, a0, n, 1);                   // 8
    k_gemm_f16 <<<gemm_blocks, 512, GEMM_SMEM>>>(nullptr, 0, 1, n);   // 9
    k_aggregate<<<agg_blocks, 256>>>(b1, a1, n, 1);                   // 10
    k_gemm_f16 <<<gemm_blocks, 512, GEMM_SMEM>>>(nullptr, 0, 2, n);   // 11
    k_aggregate<<<agg_blocks, 256>>>(b2, nullptr, n, 0);              // 12

    k_pool_sum<<<(n + 255) / 256, 128>>>(bat, n);                     // 13
    k_head<<<3, 256>>>(linW, linb, out);                              // 14
}